// round 5
// baseline (speedup 1.0000x reference)
#include <cuda_runtime.h>
#include <cuda_bf16.h>
#include <cstdint>

#define MAX_N 100000
#define MAX_E 1700000
#define FDIM  128
#define CHUNK 1024   // scan chunk (256 thr x 4)

// Scratch (allocation-free: __device__ globals)
__device__ float g_H[(size_t)MAX_N * FDIM];
__device__ float g_O[(size_t)MAX_N * FDIM];
__device__ float g_dinv[MAX_N];
__device__ float g_dinv2[MAX_N];
__device__ int   g_cnt[MAX_N];        // in-degree
__device__ int   g_pos[MAX_N];        // per-chunk exclusive scan
__device__ int   g_rowStart[MAX_N];   // CSR row offsets
__device__ int   g_wcur[MAX_N];       // scatter cursors
__device__ int   g_chunkSum[256];
__device__ int   g_es[MAX_E];         // CSR src index
__device__ float g_en[MAX_E];         // CSR edge norm

// ---------------------------------------------------------------------------
// Packed f32x2 helpers (FFMA2 — ptxas only emits it via PTX fma.rn.f32x2)
__device__ __forceinline__ unsigned long long pk_dup(float x) {
    unsigned long long r;
    asm("mov.b64 %0, {%1,%2};" : "=l"(r) : "f"(x), "f"(x));
    return r;
}
__device__ __forceinline__ void fma2(unsigned long long& d,
                                     unsigned long long a,
                                     unsigned long long b) {
    asm("fma.rn.f32x2 %0, %1, %2, %0;" : "+l"(d) : "l"(a), "l"(b));
}
__device__ __forceinline__ float2 unpk(unsigned long long v) {
    float lo, hi;
    asm("mov.b64 {%0,%1}, %2;" : "=f"(lo), "=f"(hi) : "l"(v));
    return make_float2(lo, hi);
}

// ---------------------------------------------------------------------------
__global__ void k_zero_cnt(int n) {
    int i = blockIdx.x * blockDim.x + threadIdx.x;
    if (i < n) g_cnt[i] = 0;
}

__global__ void k_hist(const int* __restrict__ ei, int E) {
    int e = blockIdx.x * blockDim.x + threadIdx.x;
    if (e < E) atomicAdd(&g_cnt[ei[E + e]], 1);
}

// Per-chunk exclusive scan: 256 threads x 4 elements = 1024 per block.
__global__ __launch_bounds__(256) void k_scan1(int n) {
    __shared__ int sh[256];
    int t = threadIdx.x;
    int base = blockIdx.x * CHUNK + t * 4;
    int v0 = (base + 0 < n) ? g_cnt[base + 0] : 0;
    int v1 = (base + 1 < n) ? g_cnt[base + 1] : 0;
    int v2 = (base + 2 < n) ? g_cnt[base + 2] : 0;
    int v3 = (base + 3 < n) ? g_cnt[base + 3] : 0;
    int tsum = v0 + v1 + v2 + v3;
    sh[t] = tsum;
    __syncthreads();
    for (int off = 1; off < 256; off <<= 1) {
        int x = (t >= off) ? sh[t - off] : 0;
        __syncthreads();
        sh[t] += x;
        __syncthreads();
    }
    int texcl = sh[t] - tsum;
    if (base + 0 < n) g_pos[base + 0] = texcl;
    if (base + 1 < n) g_pos[base + 1] = texcl + v0;
    if (base + 2 < n) g_pos[base + 2] = texcl + v0 + v1;
    if (base + 3 < n) g_pos[base + 3] = texcl + v0 + v1 + v2;
    if (t == 255) g_chunkSum[blockIdx.x] = sh[255];
}

__global__ __launch_bounds__(256) void k_scan2(int nChunks) {
    __shared__ int sh[256];
    int t = threadIdx.x;
    int v = (t < nChunks) ? g_chunkSum[t] : 0;
    sh[t] = v;
    __syncthreads();
    for (int off = 1; off < 256; off <<= 1) {
        int x = (t >= off) ? sh[t - off] : 0;
        __syncthreads();
        sh[t] += x;
        __syncthreads();
    }
    if (t < nChunks) g_chunkSum[t] = sh[t] - v;  // exclusive
}

__global__ void k_scan3(int n) {
    int i = blockIdx.x * blockDim.x + threadIdx.x;
    if (i < n) {
        int rs = g_pos[i] + g_chunkSum[i / CHUNK];
        g_rowStart[i] = rs;
        g_wcur[i]     = rs;
        float di = rsqrtf((float)g_cnt[i] + 1.0f);
        g_dinv[i]  = di;
        g_dinv2[i] = di * di;
    }
}

__global__ void k_build(const int* __restrict__ ei, int E) {
    int e = blockIdx.x * blockDim.x + threadIdx.x;
    if (e < E) {
        int s = ei[e];
        int d = ei[E + e];
        int p = atomicAdd(&g_wcur[d], 1);
        g_es[p] = s;
        g_en[p] = g_dinv[s] * g_dinv[d];
    }
}

// ---------------------------------------------------------------------------
// SGEMM with packed FFMA2: h = X @ W. 128x128 tile, 8x8 micro-tiles,
// accumulators packed as 8x4 f32x2 (cols paired).
__global__ __launch_bounds__(256) void k_gemm(
    const float* __restrict__ X, const float* __restrict__ W, int N)
{
    __shared__ float xs[32][132];   // k-major: xs[k][row]
    __shared__ float ws[32][132];   // ws[k][col]

    int t  = threadIdx.x;
    int tx = t & 15;        // col group: cols tx*8..+8
    int ty = t >> 4;        // row group: rows ty*8..+8
    int rowbase = blockIdx.x * 128;

    unsigned long long acc[8][4];
#pragma unroll
    for (int i = 0; i < 8; i++)
#pragma unroll
        for (int j = 0; j < 4; j++) acc[i][j] = 0ull;  // (0.f, 0.f)

    for (int kc = 0; kc < 128; kc += 32) {
#pragma unroll
        for (int i = 0; i < 4; i++) {
            int idx = t + i * 256;
            int row = idx >> 3;
            int kk4 = (idx & 7) * 4;
            int grow = rowbase + row;
            float4 v = (grow < N)
                ? *(const float4*)&X[(size_t)grow * FDIM + kc + kk4]
                : make_float4(0.f, 0.f, 0.f, 0.f);
            xs[kk4 + 0][row] = v.x;
            xs[kk4 + 1][row] = v.y;
            xs[kk4 + 2][row] = v.z;
            xs[kk4 + 3][row] = v.w;
        }
#pragma unroll
        for (int i = 0; i < 4; i++) {
            int idx = t + i * 256;
            int kk  = idx >> 5;
            int cc4 = (idx & 31) * 4;
            *(float4*)&ws[kk][cc4] =
                *(const float4*)&W[(size_t)(kc + kk) * FDIM + cc4];
        }
        __syncthreads();

#pragma unroll
        for (int k = 0; k < 32; k++) {
            // W pairs: reinterpret 2x float4 as 4x u64 (cols 2j, 2j+1)
            ulonglong2 w01 = *(const ulonglong2*)&ws[k][tx * 8];
            ulonglong2 w23 = *(const ulonglong2*)&ws[k][tx * 8 + 4];
            unsigned long long wp[4] = {w01.x, w01.y, w23.x, w23.y};

            float xv[8];
            *(float4*)&xv[0] = *(const float4*)&xs[k][ty * 8];
            *(float4*)&xv[4] = *(const float4*)&xs[k][ty * 8 + 4];

#pragma unroll
            for (int i = 0; i < 8; i++) {
                unsigned long long xp = pk_dup(xv[i]);
                fma2(acc[i][0], xp, wp[0]);
                fma2(acc[i][1], xp, wp[1]);
                fma2(acc[i][2], xp, wp[2]);
                fma2(acc[i][3], xp, wp[3]);
            }
        }
        __syncthreads();
    }

#pragma unroll
    for (int i = 0; i < 8; i++) {
        int grow = rowbase + ty * 8 + i;
        if (grow < N) {
            float* hp = g_H + (size_t)grow * FDIM + tx * 8;
            float2 p0 = unpk(acc[i][0]);
            float2 p1 = unpk(acc[i][1]);
            float2 p2 = unpk(acc[i][2]);
            float2 p3 = unpk(acc[i][3]);
            *(float4*)(hp)     = make_float4(p0.x, p0.y, p1.x, p1.y);
            *(float4*)(hp + 4) = make_float4(p2.x, p2.y, p3.x, p3.y);
        }
    }
}

// ---------------------------------------------------------------------------
// Pull-based aggregation + self-loop + bias + relu, fused.
// One warp per dst node; lane l owns floats [4l, 4l+4).
__global__ __launch_bounds__(256) void k_gather(
    const float* __restrict__ h, const float* __restrict__ b,
    float* __restrict__ out, int N, int relu)
{
    int warp = (blockIdx.x * 256 + threadIdx.x) >> 5;
    int lane = threadIdx.x & 31;
    if (warp >= N) return;

    int row   = warp;
    int start = g_rowStart[row];
    int cnt   = g_cnt[row];

    float d2 = g_dinv2[row];
    float4 acc = __ldg((const float4*)(h + (size_t)row * FDIM) + lane);
    acc.x *= d2; acc.y *= d2; acc.z *= d2; acc.w *= d2;

    for (int e0 = 0; e0 < cnt; e0 += 32) {
        int mye = e0 + lane;
        int s = 0; float nm = 0.f;
        if (mye < cnt) {
            s  = __ldg(&g_es[start + mye]);
            nm = __ldg(&g_en[start + mye]);
        }
        int m = min(32, cnt - e0);
#pragma unroll 4
        for (int j = 0; j < m; j++) {
            int   sj = __shfl_sync(0xffffffffu, s,  j);
            float nj = __shfl_sync(0xffffffffu, nm, j);
            float4 v = __ldg((const float4*)(h + (size_t)sj * FDIM) + lane);
            acc.x = fmaf(v.x, nj, acc.x);
            acc.y = fmaf(v.y, nj, acc.y);
            acc.z = fmaf(v.z, nj, acc.z);
            acc.w = fmaf(v.w, nj, acc.w);
        }
    }

    float4 bb = __ldg((const float4*)b + lane);
    acc.x += bb.x; acc.y += bb.y; acc.z += bb.z; acc.w += bb.w;
    if (relu) {
        acc.x = fmaxf(acc.x, 0.f); acc.y = fmaxf(acc.y, 0.f);
        acc.z = fmaxf(acc.z, 0.f); acc.w = fmaxf(acc.w, 0.f);
    }
    ((float4*)(out + (size_t)row * FDIM))[lane] = acc;
}

// ---------------------------------------------------------------------------
extern "C" void kernel_launch(void* const* d_in, const int* in_sizes, int n_in,
                              void* d_out, int out_size)
{
    const float* x  = (const float*)d_in[0];
    const int*   ei = (const int*)d_in[1];   // int32 (JAX x64 disabled)
    const float* W1 = (const float*)d_in[2];
    const float* b1 = (const float*)d_in[3];
    const float* W2 = (const float*)d_in[4];
    const float* b2 = (const float*)d_in[5];
    const float* W3 = (const float*)d_in[6];
    const float* b3 = (const float*)d_in[7];
    float* out = (float*)d_out;

    int N = in_sizes[0] / FDIM;
    int E = in_sizes[1] / 2;

    float *H, *O;
    cudaGetSymbolAddress((void**)&H, g_H);
    cudaGetSymbolAddress((void**)&O, g_O);

    int nThr = 256;
    int nBlkN    = (N + nThr - 1) / nThr;
    int nBlkE    = (E + nThr - 1) / nThr;
    int nBlkGemm = (N + 127) / 128;
    int nChunks  = (N + CHUNK - 1) / CHUNK;
    long long gthreads = (long long)N * 32;
    int nBlkGather = (int)((gthreads + nThr - 1) / nThr);

    // --- CSR build (once per launch) ---
    k_zero_cnt<<<nBlkN, nThr>>>(N);
    k_hist<<<nBlkE, nThr>>>(ei, E);
    k_scan1<<<nChunks, nThr>>>(N);
    k_scan2<<<1, nThr>>>(nChunks);
    k_scan3<<<nBlkN, nThr>>>(N);
    k_build<<<nBlkE, nThr>>>(ei, E);

    // Layer 1: x -> H -> O (relu)
    k_gemm<<<nBlkGemm, nThr>>>(x, W1, N);
    k_gather<<<nBlkGather, nThr>>>(H, b1, O, N, 1);

    // Layer 2: O -> H -> O (relu)
    k_gemm<<<nBlkGemm, nThr>>>(O, W2, N);
    k_gather<<<nBlkGather, nThr>>>(H, b2, O, N, 1);

    // Layer 3: O -> H -> out (no relu)
    k_gemm<<<nBlkGemm, nThr>>>(O, W3, N);
    k_gather<<<nBlkGather, nThr>>>(H, b3, out, N, 0);
}